// round 1
// baseline (speedup 1.0000x reference)
#include <cuda_runtime.h>

#define BATCH 4
#define SEQ   2048
#define DIM   768
#define NH    12
#define HD    64
#define BH    (BATCH*NH)          // 48
#define MROWS (BATCH*SEQ)         // 8192
#define SCALE 0.125f              // 64^-0.5

// Scratch (allocation-free rule: __device__ globals)
__device__ float g_Q[BH*SEQ*HD];
__device__ float g_K[BH*SEQ*HD];
__device__ float g_V[BH*SEQ*HD];
__device__ float g_AO[BATCH*SEQ*DIM];

// ---------------------------------------------------------------------------
// Tiled NT GEMM: C[m,c] = sum_k A[m,k] * W[c,k]
// 64x64 tile, K-tile 16, 256 threads, 4x4 per thread.
// ---------------------------------------------------------------------------
#define TILE 64
#define KT   16
#define LSTR 68   // padded stride to soften transposed-store bank conflicts

// GEMM1: qkv = x @ w_qkv^T, scattered into g_Q/g_K/g_V in [BH, SEQ, HD] layout
__global__ __launch_bounds__(256) void gemm_qkv_kernel(
    const float* __restrict__ A, const float* __restrict__ W)
{
    __shared__ float As[KT * LSTR];
    __shared__ float Ws[KT * LSTR];
    int tid = threadIdx.x;
    int tx = tid & 15, ty = tid >> 4;
    int bm = blockIdx.x * TILE;
    int bn = blockIdx.y * TILE;

    int lrow = tid >> 2;       // 0..63
    int lk   = (tid & 3) * 4;  // 0,4,8,12
    const float* aptr = A + (size_t)(bm + lrow) * DIM + lk;
    const float* wptr = W + (size_t)(bn + lrow) * DIM + lk;

    float acc[4][4];
    #pragma unroll
    for (int i = 0; i < 4; ++i)
        #pragma unroll
        for (int j = 0; j < 4; ++j) acc[i][j] = 0.f;

    for (int k0 = 0; k0 < DIM; k0 += KT) {
        float4 av = *(const float4*)(aptr + k0);
        float4 wv = *(const float4*)(wptr + k0);
        As[(lk+0)*LSTR + lrow] = av.x;
        As[(lk+1)*LSTR + lrow] = av.y;
        As[(lk+2)*LSTR + lrow] = av.z;
        As[(lk+3)*LSTR + lrow] = av.w;
        Ws[(lk+0)*LSTR + lrow] = wv.x;
        Ws[(lk+1)*LSTR + lrow] = wv.y;
        Ws[(lk+2)*LSTR + lrow] = wv.z;
        Ws[(lk+3)*LSTR + lrow] = wv.w;
        __syncthreads();
        #pragma unroll
        for (int kk = 0; kk < KT; ++kk) {
            float4 a = *(const float4*)&As[kk*LSTR + ty*4];
            float4 w = *(const float4*)&Ws[kk*LSTR + tx*4];
            acc[0][0] += a.x*w.x; acc[0][1] += a.x*w.y; acc[0][2] += a.x*w.z; acc[0][3] += a.x*w.w;
            acc[1][0] += a.y*w.x; acc[1][1] += a.y*w.y; acc[1][2] += a.y*w.z; acc[1][3] += a.y*w.w;
            acc[2][0] += a.z*w.x; acc[2][1] += a.z*w.y; acc[2][2] += a.z*w.z; acc[2][3] += a.z*w.w;
            acc[3][0] += a.w*w.x; acc[3][1] += a.w*w.y; acc[3][2] += a.w*w.z; acc[3][3] += a.w*w.w;
        }
        __syncthreads();
    }

    // Scatter epilogue: column c = s*768 + h*64 + d.  TILE=64 and bn%64==0 so
    // s and h are constant per block, d = tx*4 + j.
    int s = bn / DIM;
    int h = (bn % DIM) / HD;
    float* dst = (s == 0) ? g_Q : (s == 1) ? g_K : g_V;
    #pragma unroll
    for (int i = 0; i < 4; ++i) {
        int m = bm + ty*4 + i;
        int b = m >> 11;            // /2048
        int n = m & (SEQ - 1);
        float* drow = dst + ((size_t)(b*NH + h)*SEQ + n)*HD;
        #pragma unroll
        for (int j = 0; j < 4; ++j) drow[tx*4 + j] = acc[i][j];
    }
}

// GEMM2: out = g_AO @ w_proj^T + b_proj
__global__ __launch_bounds__(256) void gemm_proj_kernel(
    const float* __restrict__ W, const float* __restrict__ bias,
    float* __restrict__ out)
{
    __shared__ float As[KT * LSTR];
    __shared__ float Ws[KT * LSTR];
    const float* A = g_AO;
    int tid = threadIdx.x;
    int tx = tid & 15, ty = tid >> 4;
    int bm = blockIdx.x * TILE;
    int bn = blockIdx.y * TILE;

    int lrow = tid >> 2;
    int lk   = (tid & 3) * 4;
    const float* aptr = A + (size_t)(bm + lrow) * DIM + lk;
    const float* wptr = W + (size_t)(bn + lrow) * DIM + lk;

    float acc[4][4];
    #pragma unroll
    for (int i = 0; i < 4; ++i)
        #pragma unroll
        for (int j = 0; j < 4; ++j) acc[i][j] = 0.f;

    for (int k0 = 0; k0 < DIM; k0 += KT) {
        float4 av = *(const float4*)(aptr + k0);
        float4 wv = *(const float4*)(wptr + k0);
        As[(lk+0)*LSTR + lrow] = av.x;
        As[(lk+1)*LSTR + lrow] = av.y;
        As[(lk+2)*LSTR + lrow] = av.z;
        As[(lk+3)*LSTR + lrow] = av.w;
        Ws[(lk+0)*LSTR + lrow] = wv.x;
        Ws[(lk+1)*LSTR + lrow] = wv.y;
        Ws[(lk+2)*LSTR + lrow] = wv.z;
        Ws[(lk+3)*LSTR + lrow] = wv.w;
        __syncthreads();
        #pragma unroll
        for (int kk = 0; kk < KT; ++kk) {
            float4 a = *(const float4*)&As[kk*LSTR + ty*4];
            float4 w = *(const float4*)&Ws[kk*LSTR + tx*4];
            acc[0][0] += a.x*w.x; acc[0][1] += a.x*w.y; acc[0][2] += a.x*w.z; acc[0][3] += a.x*w.w;
            acc[1][0] += a.y*w.x; acc[1][1] += a.y*w.y; acc[1][2] += a.y*w.z; acc[1][3] += a.y*w.w;
            acc[2][0] += a.z*w.x; acc[2][1] += a.z*w.y; acc[2][2] += a.z*w.z; acc[2][3] += a.z*w.w;
            acc[3][0] += a.w*w.x; acc[3][1] += a.w*w.y; acc[3][2] += a.w*w.z; acc[3][3] += a.w*w.w;
        }
        __syncthreads();
    }

    #pragma unroll
    for (int i = 0; i < 4; ++i) {
        int m = bm + ty*4 + i;
        float* orow = out + (size_t)m * DIM + bn;
        #pragma unroll
        for (int j = 0; j < 4; ++j) orow[tx*4 + j] = acc[i][j] + bias[bn + tx*4 + j];
    }
}

// ---------------------------------------------------------------------------
// Flash attention (fp32): 1 thread = 1 query row. K/V tiles of 64 rows in smem.
// All smem reads are warp-uniform -> broadcast, conflict-free.
// ---------------------------------------------------------------------------
#define BR 128   // query rows per block = threads
#define BC 64    // kv rows per tile

__global__ __launch_bounds__(BR) void attn_kernel()
{
    __shared__ float Ks[BC * HD];
    __shared__ float Vs[BC * HD];

    int bh  = blockIdx.y;                       // 0..47
    int row = blockIdx.x * BR + threadIdx.x;    // 0..2047

    const float* qp = g_Q + ((size_t)bh * SEQ + row) * HD;
    float q[HD];
    #pragma unroll
    for (int u = 0; u < HD/4; ++u) {
        float4 t = *(const float4*)(qp + u*4);
        q[u*4+0] = t.x; q[u*4+1] = t.y; q[u*4+2] = t.z; q[u*4+3] = t.w;
    }

    float o[HD];
    #pragma unroll
    for (int d = 0; d < HD; ++d) o[d] = 0.f;
    float mx = -1e30f, l = 0.f;

    int r  = threadIdx.x >> 1;          // 0..63
    int cp = (threadIdx.x & 1) * 32;    // 0 or 32

    #pragma unroll 1
    for (int kt = 0; kt < SEQ/BC; ++kt) {
        const float* kp = g_K + ((size_t)bh * SEQ + kt*BC) * HD;
        const float* vp = g_V + ((size_t)bh * SEQ + kt*BC) * HD;
        #pragma unroll
        for (int u = 0; u < 8; ++u) {
            *(float4*)&Ks[r*HD + cp + u*4] = *(const float4*)(kp + r*HD + cp + u*4);
            *(float4*)&Vs[r*HD + cp + u*4] = *(const float4*)(vp + r*HD + cp + u*4);
        }
        __syncthreads();

        #pragma unroll 1
        for (int j0 = 0; j0 < BC; j0 += 8) {
            float sc[8];
            #pragma unroll
            for (int jj = 0; jj < 8; ++jj) {
                const float* kr = &Ks[(j0 + jj) * HD];
                float a0 = 0.f, a1 = 0.f;
                #pragma unroll
                for (int d4 = 0; d4 < HD/4; ++d4) {
                    float4 kv = *(const float4*)(kr + d4*4);
                    a0 += q[d4*4+0] * kv.x;
                    a1 += q[d4*4+1] * kv.y;
                    a0 += q[d4*4+2] * kv.z;
                    a1 += q[d4*4+3] * kv.w;
                }
                sc[jj] = (a0 + a1) * SCALE;
            }
            float mc = sc[0];
            #pragma unroll
            for (int jj = 1; jj < 8; ++jj) mc = fmaxf(mc, sc[jj]);
            if (mc > mx) {
                float corr = __expf(mx - mc);
                l *= corr;
                #pragma unroll
                for (int d = 0; d < HD; ++d) o[d] *= corr;
                mx = mc;
            }
            #pragma unroll
            for (int jj = 0; jj < 8; ++jj) {
                float p = __expf(sc[jj] - mx);
                l += p;
                const float* vr = &Vs[(j0 + jj) * HD];
                #pragma unroll
                for (int d4 = 0; d4 < HD/4; ++d4) {
                    float4 vv = *(const float4*)(vr + d4*4);
                    o[d4*4+0] += p * vv.x;
                    o[d4*4+1] += p * vv.y;
                    o[d4*4+2] += p * vv.z;
                    o[d4*4+3] += p * vv.w;
                }
            }
        }
        __syncthreads();
    }

    float inv = 1.f / l;
    int b = bh / NH, h = bh % NH;
    float* op = g_AO + ((size_t)(b * SEQ + row)) * DIM + h * HD;
    #pragma unroll
    for (int u = 0; u < HD/4; ++u) {
        float4 t;
        t.x = o[u*4+0] * inv; t.y = o[u*4+1] * inv;
        t.z = o[u*4+2] * inv; t.w = o[u*4+3] * inv;
        *(float4*)(op + u*4) = t;
    }
}

// ---------------------------------------------------------------------------
extern "C" void kernel_launch(void* const* d_in, const int* in_sizes, int n_in,
                              void* d_out, int out_size)
{
    const float* x      = (const float*)d_in[0];
    const float* w_qkv  = (const float*)d_in[1];
    const float* w_proj = (const float*)d_in[2];
    const float* b_proj = (const float*)d_in[3];
    float* out = (float*)d_out;

    gemm_qkv_kernel<<<dim3(MROWS/TILE, 3*DIM/TILE), 256>>>(x, w_qkv);
    attn_kernel<<<dim3(SEQ/BR, BH), BR>>>();
    gemm_proj_kernel<<<dim3(MROWS/TILE, DIM/TILE), 256>>>(w_proj, b_proj, out);
}

// round 3
// speedup vs baseline: 1.3274x; 1.3274x over previous
#include <cuda_runtime.h>
#include <cstdint>

#define BATCH 4
#define SEQ   2048
#define DIM   768
#define NH    12
#define HD    64
#define BH    (BATCH*NH)          // 48
#define MROWS (BATCH*SEQ)         // 8192
#define SCALE 0.125f

// Scratch (allocation-free rule: __device__ globals)
__device__ float g_Q[BH*SEQ*HD];
__device__ float g_K[BH*SEQ*HD];
__device__ float g_V[BH*SEQ*HD];
__device__ float g_AO[BATCH*SEQ*DIM];

__device__ __forceinline__ uint32_t f2tf32(float x) {
    uint32_t r;
    asm("cvt.rna.tf32.f32 %0, %1;" : "=r"(r) : "f"(x));
    return r;
}

__device__ __forceinline__ void mma_tf32(float c[4], uint32_t a0, uint32_t a1,
                                         uint32_t a2, uint32_t a3,
                                         uint32_t b0, uint32_t b1) {
    asm volatile(
        "mma.sync.aligned.m16n8k8.row.col.f32.tf32.tf32.f32 "
        "{%0,%1,%2,%3}, {%4,%5,%6,%7}, {%8,%9}, {%0,%1,%2,%3};"
        : "+f"(c[0]), "+f"(c[1]), "+f"(c[2]), "+f"(c[3])
        : "r"(a0), "r"(a1), "r"(a2), "r"(a3), "r"(b0), "r"(b1));
}

// ---------------------------------------------------------------------------
// mma.sync tf32 NT GEMM: C[m,c] = sum_k A[m,k] * W[c,k]
// CTA tile 128x128, K-chunk 32, 8 warps (2x4), warp tile 64x32.
// smem stride 36 words: conflict-free frag gathers (bank == lane).
// mode 0: scatter into g_Q/g_K/g_V ([BH,SEQ,HD]).  mode 1: out = C + bias.
// ---------------------------------------------------------------------------
#define KT    32
#define SSTR  36
#define SM_WORDS (2 * 128 * SSTR)   // A + B tiles

__global__ __launch_bounds__(256) void gemm_mma(
    const float* __restrict__ Ain, const float* __restrict__ W,
    const float* __restrict__ bias, float* __restrict__ out, int mode)
{
    extern __shared__ uint32_t sm[];
    uint32_t* As = sm;               // [128][36]
    uint32_t* Bs = sm + 128 * SSTR;  // [128][36]

    const float* A = Ain ? Ain : g_AO;
    int tid  = threadIdx.x;
    int w    = tid >> 5, lane = tid & 31;
    int gr   = lane >> 2, qc = lane & 3;
    int wm   = (w & 1) * 64;     // warp M offset in tile
    int wn   = (w >> 1) * 32;    // warp N offset in tile
    int bm   = blockIdx.x * 128;
    int bn   = blockIdx.y * 128;

    float acc[4][4][4];
    #pragma unroll
    for (int mt = 0; mt < 4; ++mt)
        #pragma unroll
        for (int nt = 0; nt < 4; ++nt)
            #pragma unroll
            for (int i = 0; i < 4; ++i) acc[mt][nt][i] = 0.f;

    for (int kc = 0; kc < DIM; kc += KT) {
        // Stage A and B tiles (128 rows x 32 k each), convert to tf32.
        #pragma unroll
        for (int i = 0; i < 4; ++i) {
            int e   = tid + i * 256;       // 0..1023 float4 slots
            int row = e >> 3;
            int ks4 = (e & 7) * 4;
            float4 av = *(const float4*)(A + (size_t)(bm + row) * DIM + kc + ks4);
            float4 wv = *(const float4*)(W + (size_t)(bn + row) * DIM + kc + ks4);
            uint32_t* ap = As + row * SSTR + ks4;
            uint32_t* bp = Bs + row * SSTR + ks4;
            ap[0] = f2tf32(av.x); ap[1] = f2tf32(av.y);
            ap[2] = f2tf32(av.z); ap[3] = f2tf32(av.w);
            bp[0] = f2tf32(wv.x); bp[1] = f2tf32(wv.y);
            bp[2] = f2tf32(wv.z); bp[3] = f2tf32(wv.w);
        }
        __syncthreads();

        #pragma unroll
        for (int ks = 0; ks < KT / 8; ++ks) {
            int k0 = ks * 8;
            uint32_t af[4][4], bf[4][2];
            #pragma unroll
            for (int mt = 0; mt < 4; ++mt) {
                const uint32_t* p = As + (wm + mt * 16 + gr) * SSTR + k0 + qc;
                af[mt][0] = p[0];
                af[mt][1] = p[8 * SSTR];
                af[mt][2] = p[4];
                af[mt][3] = p[8 * SSTR + 4];
            }
            #pragma unroll
            for (int nt = 0; nt < 4; ++nt) {
                const uint32_t* p = Bs + (wn + nt * 8 + gr) * SSTR + k0 + qc;
                bf[nt][0] = p[0];
                bf[nt][1] = p[4];
            }
            #pragma unroll
            for (int mt = 0; mt < 4; ++mt)
                #pragma unroll
                for (int nt = 0; nt < 4; ++nt)
                    mma_tf32(acc[mt][nt], af[mt][0], af[mt][1], af[mt][2],
                             af[mt][3], bf[nt][0], bf[nt][1]);
        }
        __syncthreads();
    }

    // Epilogue
    int scol = bn + wn;  // warp's global col base (32-wide, within one head)
    if (mode == 0) {
        int s   = scol / DIM;
        int rem = scol % DIM;
        int h   = rem / HD;
        int d0  = rem % HD;
        float* dst = (s == 0) ? g_Q : (s == 1) ? g_K : g_V;
        #pragma unroll
        for (int mt = 0; mt < 4; ++mt) {
            int r0 = bm + wm + mt * 16 + gr;
            int b  = r0 >> 11, n = r0 & (SEQ - 1);
            float* base = dst + ((size_t)(b * NH + h) * SEQ + n) * HD;
            #pragma unroll
            for (int nt = 0; nt < 4; ++nt) {
                int d = d0 + nt * 8 + 2 * qc;
                *(float2*)(base + d) = make_float2(acc[mt][nt][0], acc[mt][nt][1]);
                *(float2*)(base + 8 * HD + d) = make_float2(acc[mt][nt][2], acc[mt][nt][3]);
            }
        }
    } else {
        #pragma unroll
        for (int mt = 0; mt < 4; ++mt) {
            int r0 = bm + wm + mt * 16 + gr;
            float* base = out + (size_t)r0 * DIM;
            #pragma unroll
            for (int nt = 0; nt < 4; ++nt) {
                int cb = scol + nt * 8 + 2 * qc;
                float2 bv = *(const float2*)(bias + cb);
                *(float2*)(base + cb) =
                    make_float2(acc[mt][nt][0] + bv.x, acc[mt][nt][1] + bv.y);
                *(float2*)(base + 8 * DIM + cb) =
                    make_float2(acc[mt][nt][2] + bv.x, acc[mt][nt][3] + bv.y);
            }
        }
    }
}

// ---------------------------------------------------------------------------
// Flash attention (fp32): 1 thread = 1 query row. K/V tiles of 64 rows in smem.
// ---------------------------------------------------------------------------
#define BR 128
#define BC 64

__global__ __launch_bounds__(BR) void attn_kernel()
{
    __shared__ float Ks[BC * HD];
    __shared__ float Vs[BC * HD];

    int bh  = blockIdx.y;
    int row = blockIdx.x * BR + threadIdx.x;

    const float* qp = g_Q + ((size_t)bh * SEQ + row) * HD;
    float q[HD];
    #pragma unroll
    for (int u = 0; u < HD/4; ++u) {
        float4 t = *(const float4*)(qp + u*4);
        q[u*4+0] = t.x; q[u*4+1] = t.y; q[u*4+2] = t.z; q[u*4+3] = t.w;
    }

    float o[HD];
    #pragma unroll
    for (int d = 0; d < HD; ++d) o[d] = 0.f;
    float mx = -1e30f, l = 0.f;

    int r  = threadIdx.x >> 1;
    int cp = (threadIdx.x & 1) * 32;

    #pragma unroll 1
    for (int kt = 0; kt < SEQ/BC; ++kt) {
        const float* kp = g_K + ((size_t)bh * SEQ + kt*BC) * HD;
        const float* vp = g_V + ((size_t)bh * SEQ + kt*BC) * HD;
        #pragma unroll
        for (int u = 0; u < 8; ++u) {
            *(float4*)&Ks[r*HD + cp + u*4] = *(const float4*)(kp + r*HD + cp + u*4);
            *(float4*)&Vs[r*HD + cp + u*4] = *(const float4*)(vp + r*HD + cp + u*4);
        }
        __syncthreads();

        #pragma unroll 1
        for (int j0 = 0; j0 < BC; j0 += 8) {
            float sc[8];
            #pragma unroll
            for (int jj = 0; jj < 8; ++jj) {
                const float* kr = &Ks[(j0 + jj) * HD];
                float a0 = 0.f, a1 = 0.f;
                #pragma unroll
                for (int d4 = 0; d4 < HD/4; ++d4) {
                    float4 kv = *(const float4*)(kr + d4*4);
                    a0 += q[d4*4+0] * kv.x;
                    a1 += q[d4*4+1] * kv.y;
                    a0 += q[d4*4+2] * kv.z;
                    a1 += q[d4*4+3] * kv.w;
                }
                sc[jj] = (a0 + a1) * SCALE;
            }
            float mc = sc[0];
            #pragma unroll
            for (int jj = 1; jj < 8; ++jj) mc = fmaxf(mc, sc[jj]);
            if (mc > mx) {
                float corr = __expf(mx - mc);
                l *= corr;
                #pragma unroll
                for (int d = 0; d < HD; ++d) o[d] *= corr;
                mx = mc;
            }
            #pragma unroll
            for (int jj = 0; jj < 8; ++jj) {
                float p = __expf(sc[jj] - mx);
                l += p;
                const float* vr = &Vs[(j0 + jj) * HD];
                #pragma unroll
                for (int d4 = 0; d4 < HD/4; ++d4) {
                    float4 vv = *(const float4*)(vr + d4*4);
                    o[d4*4+0] += p * vv.x;
                    o[d4*4+1] += p * vv.y;
                    o[d4*4+2] += p * vv.z;
                    o[d4*4+3] += p * vv.w;
                }
            }
        }
        __syncthreads();
    }

    float inv = 1.f / l;
    int b = bh / NH, h = bh % NH;
    float* op = g_AO + ((size_t)(b * SEQ + row)) * DIM + h * HD;
    #pragma unroll
    for (int u = 0; u < HD/4; ++u) {
        float4 t;
        t.x = o[u*4+0] * inv; t.y = o[u*4+1] * inv;
        t.z = o[u*4+2] * inv; t.w = o[u*4+3] * inv;
        *(float4*)(op + u*4) = t;
    }
}

// ---------------------------------------------------------------------------
extern "C" void kernel_launch(void* const* d_in, const int* in_sizes, int n_in,
                              void* d_out, int out_size)
{
    const float* x      = (const float*)d_in[0];
    const float* w_qkv  = (const float*)d_in[1];
    const float* w_proj = (const float*)d_in[2];
    const float* b_proj = (const float*)d_in[3];
    float* out = (float*)d_out;

    size_t smem = SM_WORDS * sizeof(uint32_t);  // 36 KB
    gemm_mma<<<dim3(MROWS/128, 3*DIM/128), 256, smem>>>(x, w_qkv, nullptr, nullptr, 0);
    attn_kernel<<<dim3(SEQ/BR, BH), BR>>>();
    gemm_mma<<<dim3(MROWS/128, DIM/128), 256, smem>>>(nullptr, w_proj, b_proj, out, 1);
}

// round 4
// speedup vs baseline: 3.8943x; 2.9339x over previous
#include <cuda_runtime.h>
#include <cstdint>

#define BATCH 4
#define SEQ   2048
#define DIM   768
#define NH    12
#define HD    64
#define BH    (BATCH*NH)          // 48
#define MROWS (BATCH*SEQ)         // 8192
#define SCALE 0.125f

// Scratch (allocation-free rule: __device__ globals)
__device__ float g_Q[BH*SEQ*HD];
__device__ float g_K[BH*SEQ*HD];
__device__ float g_V[BH*SEQ*HD];
__device__ float g_AO[BATCH*SEQ*DIM];

__device__ __forceinline__ uint32_t f2tf32(float x) {
    uint32_t r;
    asm("cvt.rna.tf32.f32 %0, %1;" : "=r"(r) : "f"(x));
    return r;
}

__device__ __forceinline__ void mma_tf32(float c[4], uint32_t a0, uint32_t a1,
                                         uint32_t a2, uint32_t a3,
                                         uint32_t b0, uint32_t b1) {
    asm volatile(
        "mma.sync.aligned.m16n8k8.row.col.f32.tf32.tf32.f32 "
        "{%0,%1,%2,%3}, {%4,%5,%6,%7}, {%8,%9}, {%0,%1,%2,%3};"
        : "+f"(c[0]), "+f"(c[1]), "+f"(c[2]), "+f"(c[3])
        : "r"(a0), "r"(a1), "r"(a2), "r"(a3), "r"(b0), "r"(b1));
}

// ---------------------------------------------------------------------------
// mma.sync tf32 NT GEMM (unchanged from R3, validated)
// ---------------------------------------------------------------------------
#define KT    32
#define SSTR  36
#define SM_WORDS (2 * 128 * SSTR)

__global__ __launch_bounds__(256) void gemm_mma(
    const float* __restrict__ Ain, const float* __restrict__ W,
    const float* __restrict__ bias, float* __restrict__ out, int mode)
{
    extern __shared__ uint32_t sm[];
    uint32_t* As = sm;
    uint32_t* Bs = sm + 128 * SSTR;

    const float* A = Ain ? Ain : g_AO;
    int tid  = threadIdx.x;
    int w    = tid >> 5, lane = tid & 31;
    int gr   = lane >> 2, qc = lane & 3;
    int wm   = (w & 1) * 64;
    int wn   = (w >> 1) * 32;
    int bm   = blockIdx.x * 128;
    int bn   = blockIdx.y * 128;

    float acc[4][4][4];
    #pragma unroll
    for (int mt = 0; mt < 4; ++mt)
        #pragma unroll
        for (int nt = 0; nt < 4; ++nt)
            #pragma unroll
            for (int i = 0; i < 4; ++i) acc[mt][nt][i] = 0.f;

    for (int kc = 0; kc < DIM; kc += KT) {
        #pragma unroll
        for (int i = 0; i < 4; ++i) {
            int e   = tid + i * 256;
            int row = e >> 3;
            int ks4 = (e & 7) * 4;
            float4 av = *(const float4*)(A + (size_t)(bm + row) * DIM + kc + ks4);
            float4 wv = *(const float4*)(W + (size_t)(bn + row) * DIM + kc + ks4);
            uint32_t* ap = As + row * SSTR + ks4;
            uint32_t* bp = Bs + row * SSTR + ks4;
            ap[0] = f2tf32(av.x); ap[1] = f2tf32(av.y);
            ap[2] = f2tf32(av.z); ap[3] = f2tf32(av.w);
            bp[0] = f2tf32(wv.x); bp[1] = f2tf32(wv.y);
            bp[2] = f2tf32(wv.z); bp[3] = f2tf32(wv.w);
        }
        __syncthreads();

        #pragma unroll
        for (int ks = 0; ks < KT / 8; ++ks) {
            int k0 = ks * 8;
            uint32_t af[4][4], bf[4][2];
            #pragma unroll
            for (int mt = 0; mt < 4; ++mt) {
                const uint32_t* p = As + (wm + mt * 16 + gr) * SSTR + k0 + qc;
                af[mt][0] = p[0];
                af[mt][1] = p[8 * SSTR];
                af[mt][2] = p[4];
                af[mt][3] = p[8 * SSTR + 4];
            }
            #pragma unroll
            for (int nt = 0; nt < 4; ++nt) {
                const uint32_t* p = Bs + (wn + nt * 8 + gr) * SSTR + k0 + qc;
                bf[nt][0] = p[0];
                bf[nt][1] = p[4];
            }
            #pragma unroll
            for (int mt = 0; mt < 4; ++mt)
                #pragma unroll
                for (int nt = 0; nt < 4; ++nt)
                    mma_tf32(acc[mt][nt], af[mt][0], af[mt][1], af[mt][2],
                             af[mt][3], bf[nt][0], bf[nt][1]);
        }
        __syncthreads();
    }

    int scol = bn + wn;
    if (mode == 0) {
        int s   = scol / DIM;
        int rem = scol % DIM;
        int h   = rem / HD;
        int d0  = rem % HD;
        float* dst = (s == 0) ? g_Q : (s == 1) ? g_K : g_V;
        #pragma unroll
        for (int mt = 0; mt < 4; ++mt) {
            int r0 = bm + wm + mt * 16 + gr;
            int b  = r0 >> 11, n = r0 & (SEQ - 1);
            float* base = dst + ((size_t)(b * NH + h) * SEQ + n) * HD;
            #pragma unroll
            for (int nt = 0; nt < 4; ++nt) {
                int d = d0 + nt * 8 + 2 * qc;
                *(float2*)(base + d) = make_float2(acc[mt][nt][0], acc[mt][nt][1]);
                *(float2*)(base + 8 * HD + d) = make_float2(acc[mt][nt][2], acc[mt][nt][3]);
            }
        }
    } else {
        #pragma unroll
        for (int mt = 0; mt < 4; ++mt) {
            int r0 = bm + wm + mt * 16 + gr;
            float* base = out + (size_t)r0 * DIM;
            #pragma unroll
            for (int nt = 0; nt < 4; ++nt) {
                int cb = scol + nt * 8 + 2 * qc;
                float2 bv = *(const float2*)(bias + cb);
                *(float2*)(base + cb) =
                    make_float2(acc[mt][nt][0] + bv.x, acc[mt][nt][1] + bv.y);
                *(float2*)(base + 8 * DIM + cb) =
                    make_float2(acc[mt][nt][2] + bv.x, acc[mt][nt][3] + bv.y);
            }
        }
    }
}

// ---------------------------------------------------------------------------
// Flash attention with mma.sync tf32.
// CTA: 128 Q rows, 8 warps (16 rows each), KV tiles of 64.
// smem: Ks[64][68] natural, Vs[64][68] = V^T ([dim][key]), Ps[128][68].
// ---------------------------------------------------------------------------
#define ABR 128
#define ABC 64
#define PSTR 68
#define ATT_SMEM ((64 + 64 + 128) * PSTR * 4)   // 69632 bytes

__global__ __launch_bounds__(256) void attn_mma()
{
    extern __shared__ float sh[];
    float* Ks = sh;                  // [64][PSTR]
    float* Vs = sh + 64 * PSTR;      // [64][PSTR]  (V transposed: [dim][key])
    float* Ps = sh + 128 * PSTR;     // [128][PSTR]

    int bh  = blockIdx.y;
    int q0  = blockIdx.x * ABR;
    int tid = threadIdx.x;
    int w   = tid >> 5, lane = tid & 31;
    int gr  = lane >> 2, qc = lane & 3;
    int wm  = w * 16;

    const float* Qb = g_Q + ((size_t)bh * SEQ + q0) * HD;
    const float* Kb = g_K + (size_t)bh * SEQ * HD;
    const float* Vb = g_V + (size_t)bh * SEQ * HD;

    // Q fragments, pre-scaled by SCALE (exact power of 2), tf32-rounded.
    int r0 = wm + gr;
    uint32_t qf[8][4];
    #pragma unroll
    for (int kt = 0; kt < 8; ++kt) {
        int c = kt * 8 + qc;
        qf[kt][0] = f2tf32(Qb[(size_t)r0 * HD + c] * SCALE);
        qf[kt][1] = f2tf32(Qb[(size_t)(r0 + 8) * HD + c] * SCALE);
        qf[kt][2] = f2tf32(Qb[(size_t)r0 * HD + c + 4] * SCALE);
        qf[kt][3] = f2tf32(Qb[(size_t)(r0 + 8) * HD + c + 4] * SCALE);
    }

    float of[8][4];
    #pragma unroll
    for (int nt = 0; nt < 8; ++nt)
        #pragma unroll
        for (int i = 0; i < 4; ++i) of[nt][i] = 0.f;
    float m0 = -1e30f, m1 = -1e30f, l0 = 0.f, l1 = 0.f;

    #pragma unroll 1
    for (int t = 0; t < SEQ / ABC; ++t) {
        const float* Kt = Kb + (size_t)t * ABC * HD;
        const float* Vt = Vb + (size_t)t * ABC * HD;

        // Stage K natural [key][dim] (coalesced loads, contiguous stores).
        #pragma unroll
        for (int i = 0; i < 4; ++i) {
            int slot = tid + i * 256;
            int key  = slot >> 4;
            int d4   = (slot & 15) * 4;
            float4 kv = *(const float4*)(Kt + key * HD + d4);
            float* p = Ks + key * PSTR + d4;
            p[0] = __uint_as_float(f2tf32(kv.x));
            p[1] = __uint_as_float(f2tf32(kv.y));
            p[2] = __uint_as_float(f2tf32(kv.z));
            p[3] = __uint_as_float(f2tf32(kv.w));
        }
        // Stage V transposed [dim][key] (lanes span keys -> conflict-free STS).
        #pragma unroll
        for (int i = 0; i < 4; ++i) {
            int slot = tid + i * 256;
            int key  = slot & 63;
            int d4   = (slot >> 6) * 4;
            float4 vv = *(const float4*)(Vt + key * HD + d4);
            Vs[(d4 + 0) * PSTR + key] = __uint_as_float(f2tf32(vv.x));
            Vs[(d4 + 1) * PSTR + key] = __uint_as_float(f2tf32(vv.y));
            Vs[(d4 + 2) * PSTR + key] = __uint_as_float(f2tf32(vv.z));
            Vs[(d4 + 3) * PSTR + key] = __uint_as_float(f2tf32(vv.w));
        }
        __syncthreads();

        // S = Q K^T  (warp: 16 rows x 64 keys)
        float sf[8][4];
        #pragma unroll
        for (int nt = 0; nt < 8; ++nt)
            #pragma unroll
            for (int i = 0; i < 4; ++i) sf[nt][i] = 0.f;
        #pragma unroll
        for (int kt = 0; kt < 8; ++kt) {
            int k0 = kt * 8;
            #pragma unroll
            for (int nt = 0; nt < 8; ++nt) {
                const uint32_t* bp =
                    (const uint32_t*)(Ks + (nt * 8 + gr) * PSTR + k0 + qc);
                mma_tf32(sf[nt], qf[kt][0], qf[kt][1], qf[kt][2], qf[kt][3],
                         bp[0], bp[4]);
            }
        }

        // Online softmax
        float tm0 = -1e30f, tm1 = -1e30f;
        #pragma unroll
        for (int nt = 0; nt < 8; ++nt) {
            tm0 = fmaxf(tm0, fmaxf(sf[nt][0], sf[nt][1]));
            tm1 = fmaxf(tm1, fmaxf(sf[nt][2], sf[nt][3]));
        }
        tm0 = fmaxf(tm0, __shfl_xor_sync(0xffffffffu, tm0, 1));
        tm0 = fmaxf(tm0, __shfl_xor_sync(0xffffffffu, tm0, 2));
        tm1 = fmaxf(tm1, __shfl_xor_sync(0xffffffffu, tm1, 1));
        tm1 = fmaxf(tm1, __shfl_xor_sync(0xffffffffu, tm1, 2));

        float nm0 = fmaxf(m0, tm0), nm1 = fmaxf(m1, tm1);
        float c0 = __expf(m0 - nm0), c1 = __expf(m1 - nm1);
        m0 = nm0; m1 = nm1;

        float rs0 = 0.f, rs1 = 0.f;
        float* prow0 = Ps + (wm + gr) * PSTR + 2 * qc;
        float* prow1 = prow0 + 8 * PSTR;
        #pragma unroll
        for (int nt = 0; nt < 8; ++nt) {
            // Round p to tf32 BEFORE accumulating l so num/denom bias cancels.
            float p0 = __uint_as_float(f2tf32(__expf(sf[nt][0] - nm0)));
            float p1 = __uint_as_float(f2tf32(__expf(sf[nt][1] - nm0)));
            float p2 = __uint_as_float(f2tf32(__expf(sf[nt][2] - nm1)));
            float p3 = __uint_as_float(f2tf32(__expf(sf[nt][3] - nm1)));
            rs0 += p0 + p1;
            rs1 += p2 + p3;
            *(float2*)(prow0 + nt * 8) = make_float2(p0, p1);
            *(float2*)(prow1 + nt * 8) = make_float2(p2, p3);
        }
        rs0 += __shfl_xor_sync(0xffffffffu, rs0, 1);
        rs0 += __shfl_xor_sync(0xffffffffu, rs0, 2);
        rs1 += __shfl_xor_sync(0xffffffffu, rs1, 1);
        rs1 += __shfl_xor_sync(0xffffffffu, rs1, 2);
        l0 = l0 * c0 + rs0;
        l1 = l1 * c1 + rs1;

        #pragma unroll
        for (int nt = 0; nt < 8; ++nt) {
            of[nt][0] *= c0; of[nt][1] *= c0;
            of[nt][2] *= c1; of[nt][3] *= c1;
        }
        __syncthreads();  // Ps visible to all warps of this warp's rows? (own rows only) — kept for Vs/Ks reuse ordering

        // O += P V   (A from Ps, B from Vs)
        #pragma unroll
        for (int kt = 0; kt < 8; ++kt) {
            int k0 = kt * 8;
            const uint32_t* ap =
                (const uint32_t*)(Ps + (wm + gr) * PSTR + k0 + qc);
            uint32_t a0 = ap[0];
            uint32_t a1 = ap[8 * PSTR];
            uint32_t a2 = ap[4];
            uint32_t a3 = ap[8 * PSTR + 4];
            #pragma unroll
            for (int nt = 0; nt < 8; ++nt) {
                const uint32_t* bp =
                    (const uint32_t*)(Vs + (nt * 8 + gr) * PSTR + k0 + qc);
                mma_tf32(of[nt], a0, a1, a2, a3, bp[0], bp[4]);
            }
        }
        __syncthreads();
    }

    // Epilogue
    float inv0 = 1.f / l0, inv1 = 1.f / l1;
    int b = bh / NH, h = bh % NH;
    int n0 = q0 + wm + gr;
    float* o0 = g_AO + ((size_t)(b * SEQ + n0)) * DIM + h * HD;
    float* o1 = g_AO + ((size_t)(b * SEQ + n0 + 8)) * DIM + h * HD;
    #pragma unroll
    for (int nt = 0; nt < 8; ++nt) {
        int d = nt * 8 + 2 * qc;
        *(float2*)(o0 + d) = make_float2(of[nt][0] * inv0, of[nt][1] * inv0);
        *(float2*)(o1 + d) = make_float2(of[nt][2] * inv1, of[nt][3] * inv1);
    }
}

// ---------------------------------------------------------------------------
extern "C" void kernel_launch(void* const* d_in, const int* in_sizes, int n_in,
                              void* d_out, int out_size)
{
    const float* x      = (const float*)d_in[0];
    const float* w_qkv  = (const float*)d_in[1];
    const float* w_proj = (const float*)d_in[2];
    const float* b_proj = (const float*)d_in[3];
    float* out = (float*)d_out;

    cudaFuncSetAttribute(attn_mma, cudaFuncAttributeMaxDynamicSharedMemorySize,
                         ATT_SMEM);

    size_t smem = SM_WORDS * sizeof(uint32_t);  // 36 KB
    gemm_mma<<<dim3(MROWS/128, 3*DIM/128), 256, smem>>>(x, w_qkv, nullptr, nullptr, 0);
    attn_mma<<<dim3(SEQ/ABR, BH), 256, ATT_SMEM>>>();
    gemm_mma<<<dim3(MROWS/128, DIM/128), 256, smem>>>(nullptr, w_proj, b_proj, out, 1);
}